// round 1
// baseline (speedup 1.0000x reference)
#include <cuda_runtime.h>
#include <cuda_bf16.h>
#include <mma.h>

using namespace nvcuda;

// Problem constants
#define BATCH 2
#define SEQ   2048
#define DMODEL 1024
#define NHEAD 16
#define DHEAD 64
#define MTOK  (BATCH*SEQ)          // 4096
#define EPS   1e-5f

// ---------------- static device scratch (no allocs allowed) ----------------
__device__ float          g_xn [MTOK*DMODEL];   // normalized x, fp32 (residual)
__device__ __nv_bfloat16  g_xnb[MTOK*DMODEL];   // normalized x, bf16 (GEMM A)
__device__ __nv_bfloat16  g_q  [MTOK*DMODEL];   // [B,H,T,D]
__device__ __nv_bfloat16  g_k  [MTOK*DMODEL];   // [B,H,T,D]
__device__ __nv_bfloat16  g_v  [MTOK*DMODEL];   // [B,H,T,D]
__device__ __nv_bfloat16  g_o  [MTOK*DMODEL];   // [B,T,H*D] (token-major)

// ---------------- LayerNorm ----------------
__global__ __launch_bounds__(256)
void ln_kernel(const float* __restrict__ x,
               const float* __restrict__ gamma,
               const float* __restrict__ beta)
{
    __shared__ float red1[8], red2[8];
    __shared__ float s_mean, s_rstd;
    const int row = blockIdx.x;
    const int tid = threadIdx.x;

    float4 v = ((const float4*)(x + (size_t)row*DMODEL))[tid];
    float s1 = v.x + v.y + v.z + v.w;
    float s2 = v.x*v.x + v.y*v.y + v.z*v.z + v.w*v.w;
    #pragma unroll
    for (int o = 16; o > 0; o >>= 1) {
        s1 += __shfl_xor_sync(0xffffffffu, s1, o);
        s2 += __shfl_xor_sync(0xffffffffu, s2, o);
    }
    if ((tid & 31) == 0) { red1[tid >> 5] = s1; red2[tid >> 5] = s2; }
    __syncthreads();
    if (tid == 0) {
        float t1 = 0.f, t2 = 0.f;
        #pragma unroll
        for (int i = 0; i < 8; i++) { t1 += red1[i]; t2 += red2[i]; }
        float mean = t1 * (1.f/DMODEL);
        float var  = t2 * (1.f/DMODEL) - mean*mean;
        s_mean = mean;
        s_rstd = rsqrtf(var + EPS);
    }
    __syncthreads();
    const float mean = s_mean, rstd = s_rstd;

    float4 g  = ((const float4*)gamma)[tid];
    float4 bt = ((const float4*)beta )[tid];
    float4 o;
    o.x = (v.x - mean)*rstd*g.x + bt.x;
    o.y = (v.y - mean)*rstd*g.y + bt.y;
    o.z = (v.z - mean)*rstd*g.z + bt.z;
    o.w = (v.w - mean)*rstd*g.w + bt.w;
    ((float4*)(g_xn + (size_t)row*DMODEL))[tid] = o;
    __nv_bfloat162* dst = (__nv_bfloat162*)(g_xnb + (size_t)row*DMODEL);
    dst[2*tid]   = __floats2bfloat162_rn(o.x, o.y);
    dst[2*tid+1] = __floats2bfloat162_rn(o.z, o.w);
}

// ---------------- GEMM: [4096,1024] @ [1024,1024] ----------------
// mode 0/1/2: A=g_xnb, out bf16 to g_q/g_k/g_v with [B,H,T,D] remap
// mode 3:     A=g_o,   out fp32 = acc + bias[n] + g_xn[m,n]  (final output)
#define BM 128
#define BN 128
#define BK 32
#define LDA 40
#define LDB 136
#define LDS 132
#define GEMM_SMEM (BM*LDS*4)

__global__ __launch_bounds__(256)
void gemm_kernel(const float* __restrict__ W,
                 const float* __restrict__ bias,
                 float* __restrict__ outf,
                 int mode)
{
    extern __shared__ char smem_raw[];
    __nv_bfloat16* As = (__nv_bfloat16*)smem_raw;       // [BM][LDA]
    __nv_bfloat16* Bs = As + BM*LDA;                    // [BK][LDB]
    float* stage = (float*)smem_raw;                    // [BM][LDS] (reused)

    const __nv_bfloat16* A = (mode == 3) ? g_o : g_xnb;
    __nv_bfloat16* outb = (mode == 0) ? g_q : (mode == 1) ? g_k :
                          (mode == 2) ? g_v : nullptr;

    const int tid = threadIdx.x;
    const int w  = tid >> 5;
    const int wm = w >> 1, wn = w & 1;          // 4 x 2 warp grid
    const int bn = blockIdx.x, bm = blockIdx.y;

    wmma::fragment<wmma::accumulator,16,16,16,float> acc[2][4];
    #pragma unroll
    for (int i = 0; i < 2; i++)
        #pragma unroll
        for (int j = 0; j < 4; j++) wmma::fill_fragment(acc[i][j], 0.0f);

    for (int k0 = 0; k0 < DMODEL; k0 += BK) {
        __syncthreads();
        // A tile: 128x32 bf16, vectorized 16B
        #pragma unroll
        for (int l = 0; l < 2; l++) {
            int vi = tid + l*256;
            int r = vi >> 2, c = (vi & 3) << 3;
            *(uint4*)(As + r*LDA + c) =
                *(const uint4*)(A + (size_t)(bm*BM + r)*DMODEL + k0 + c);
        }
        // W tile: 32x128 fp32 -> bf16
        #pragma unroll
        for (int l = 0; l < 4; l++) {
            int vi = tid + l*256;
            int r = vi >> 5, c = (vi & 31) << 2;
            float4 val = *(const float4*)(W + (size_t)(k0 + r)*DMODEL + bn*BN + c);
            __nv_bfloat16* d = Bs + r*LDB + c;
            d[0] = __float2bfloat16(val.x);
            d[1] = __float2bfloat16(val.y);
            d[2] = __float2bfloat16(val.z);
            d[3] = __float2bfloat16(val.w);
        }
        __syncthreads();
        #pragma unroll
        for (int ks = 0; ks < BK; ks += 16) {
            wmma::fragment<wmma::matrix_a,16,16,16,__nv_bfloat16,wmma::row_major> af[2];
            wmma::fragment<wmma::matrix_b,16,16,16,__nv_bfloat16,wmma::row_major> bf[4];
            #pragma unroll
            for (int mi = 0; mi < 2; mi++)
                wmma::load_matrix_sync(af[mi], As + (wm*32 + mi*16)*LDA + ks, LDA);
            #pragma unroll
            for (int ni = 0; ni < 4; ni++)
                wmma::load_matrix_sync(bf[ni], Bs + ks*LDB + wn*64 + ni*16, LDB);
            #pragma unroll
            for (int mi = 0; mi < 2; mi++)
                #pragma unroll
                for (int ni = 0; ni < 4; ni++)
                    wmma::mma_sync(acc[mi][ni], af[mi], bf[ni], acc[mi][ni]);
        }
    }

    __syncthreads();
    #pragma unroll
    for (int mi = 0; mi < 2; mi++)
        #pragma unroll
        for (int ni = 0; ni < 4; ni++)
            wmma::store_matrix_sync(stage + (wm*32 + mi*16)*LDS + wn*64 + ni*16,
                                    acc[mi][ni], LDS, wmma::mem_row_major);
    __syncthreads();

    if (mode == 3) {
        #pragma unroll 8
        for (int e = 0; e < 64; e++) {
            int idx = tid + e*256;
            int r = idx >> 7, c = idx & 127;
            int m = bm*BM + r, n = bn*BN + c;
            outf[(size_t)m*DMODEL + n] =
                stage[r*LDS + c] + bias[n] + g_xn[(size_t)m*DMODEL + n];
        }
    } else {
        #pragma unroll 8
        for (int e = 0; e < 64; e++) {
            int idx = tid + e*256;
            int r = idx >> 7, c = idx & 127;
            int m = bm*BM + r, n = bn*BN + c;
            int b = m >> 11, t = m & 2047;
            int h = n >> 6,  d = n & 63;
            outb[(((size_t)(b*NHEAD + h))*SEQ + t)*DHEAD + d] =
                __float2bfloat16(stage[r*LDS + c]);
        }
    }
}

// ---------------- Flash attention (causal) ----------------
// grid: (qtile=16, head=16, batch=2), 256 threads.
#define AQ 128
#define AK 64
#define QLD 72
#define SLD 68
#define ATTN_SMEM ((AQ*QLD + 2*AK*QLD + AQ*QLD)*2 + (2*AQ*SLD + 3*AQ)*4)

__global__ __launch_bounds__(256)
void attn_kernel()
{
    extern __shared__ char smem_raw[];
    __nv_bfloat16* Qs = (__nv_bfloat16*)smem_raw;  // [128][72]
    __nv_bfloat16* Ks = Qs + AQ*QLD;               // [64][72]
    __nv_bfloat16* Vs = Ks + AK*QLD;               // [64][72]
    __nv_bfloat16* Ps = Vs + AK*QLD;               // [128][72]
    float* Ss  = (float*)(Ps + AQ*QLD);            // [128][68] (S then PV stage)
    float* Os  = Ss + AQ*SLD;                      // [128][68]
    float* m_s = Os + AQ*SLD;
    float* l_s = m_s + AQ;
    float* al  = l_s + AQ;

    const int tid = threadIdx.x;
    const int w = tid >> 5, wm = w >> 1, wn = w & 1;
    const int qi = blockIdx.x, h = blockIdx.y, b = blockIdx.z;

    const size_t head_base = ((size_t)(b*NHEAD + h)) * SEQ * DHEAD;

    // Load Q tile
    const __nv_bfloat16* qptr = g_q + head_base + (size_t)qi*AQ*DHEAD;
    #pragma unroll
    for (int l = 0; l < 4; l++) {
        int vi = tid + l*256;
        int r = vi >> 3, c = (vi & 7) << 3;
        *(uint4*)(Qs + r*QLD + c) = *(const uint4*)(qptr + r*DHEAD + c);
    }
    #pragma unroll
    for (int e = 0; e < 32; e++) {
        int i = tid + e*256;
        Os[(i >> 6)*SLD + (i & 63)] = 0.f;
    }
    if (tid < AQ) { m_s[tid] = -INFINITY; l_s[tid] = 0.f; }
    __syncthreads();

    const int jmax = 2*qi + 1;
    for (int j = 0; j <= jmax; j++) {
        // Load K/V tiles
        const __nv_bfloat16* kptr = g_k + head_base + (size_t)j*AK*DHEAD;
        const __nv_bfloat16* vptr = g_v + head_base + (size_t)j*AK*DHEAD;
        #pragma unroll
        for (int l = 0; l < 2; l++) {
            int vi = tid + l*256;
            int r = vi >> 3, c = (vi & 7) << 3;
            *(uint4*)(Ks + r*QLD + c) = *(const uint4*)(kptr + r*DHEAD + c);
            *(uint4*)(Vs + r*QLD + c) = *(const uint4*)(vptr + r*DHEAD + c);
        }
        __syncthreads();

        // S = Q @ K^T  (128x64)
        {
            wmma::fragment<wmma::accumulator,16,16,16,float> sacc[2][2];
            #pragma unroll
            for (int mi = 0; mi < 2; mi++)
                #pragma unroll
                for (int ni = 0; ni < 2; ni++) wmma::fill_fragment(sacc[mi][ni], 0.f);
            #pragma unroll
            for (int ks = 0; ks < 4; ks++) {
                wmma::fragment<wmma::matrix_a,16,16,16,__nv_bfloat16,wmma::row_major> af[2];
                wmma::fragment<wmma::matrix_b,16,16,16,__nv_bfloat16,wmma::col_major> bf[2];
                #pragma unroll
                for (int mi = 0; mi < 2; mi++)
                    wmma::load_matrix_sync(af[mi], Qs + (wm*32 + mi*16)*QLD + ks*16, QLD);
                #pragma unroll
                for (int ni = 0; ni < 2; ni++)
                    wmma::load_matrix_sync(bf[ni], Ks + (wn*32 + ni*16)*QLD + ks*16, QLD);
                #pragma unroll
                for (int mi = 0; mi < 2; mi++)
                    #pragma unroll
                    for (int ni = 0; ni < 2; ni++)
                        wmma::mma_sync(sacc[mi][ni], af[mi], bf[ni], sacc[mi][ni]);
            }
            #pragma unroll
            for (int mi = 0; mi < 2; mi++)
                #pragma unroll
                for (int ni = 0; ni < 2; ni++)
                    wmma::store_matrix_sync(Ss + (wm*32 + mi*16)*SLD + wn*32 + ni*16,
                                            sacc[mi][ni], SLD, wmma::mem_row_major);
        }
        __syncthreads();

        // online softmax (one thread per query row)
        if (tid < AQ) {
            const int r = tid;
            const int qglob = qi*AQ + r;
            int cnt = qglob - j*AK + 1;
            cnt = cnt > AK ? AK : cnt;
            float mold = m_s[r];
            float tmax = -INFINITY;
            for (int c = 0; c < cnt; c++) {
                float s = Ss[r*SLD + c] * 0.125f;   // 1/sqrt(64)
                Ss[r*SLD + c] = s;
                tmax = fmaxf(tmax, s);
            }
            float mnew = fmaxf(mold, tmax);
            float alpha = __expf(mold - mnew);
            float sum = 0.f;
            for (int c = 0; c < AK; c++) {
                float p = 0.f;
                if (c < cnt) { p = __expf(Ss[r*SLD + c] - mnew); sum += p; }
                Ps[r*QLD + c] = __float2bfloat16(p);
            }
            l_s[r] = l_s[r]*alpha + sum;
            al[r]  = alpha;
            m_s[r] = mnew;
        }
        __syncthreads();

        // PV = P @ V  (128x64) -> stage into Ss
        {
            wmma::fragment<wmma::accumulator,16,16,16,float> pacc[2][2];
            #pragma unroll
            for (int mi = 0; mi < 2; mi++)
                #pragma unroll
                for (int ni = 0; ni < 2; ni++) wmma::fill_fragment(pacc[mi][ni], 0.f);
            #pragma unroll
            for (int ks = 0; ks < 4; ks++) {
                wmma::fragment<wmma::matrix_a,16,16,16,__nv_bfloat16,wmma::row_major> af[2];
                wmma::fragment<wmma::matrix_b,16,16,16,__nv_bfloat16,wmma::row_major> bf[2];
                #pragma unroll
                for (int mi = 0; mi < 2; mi++)
                    wmma::load_matrix_sync(af[mi], Ps + (wm*32 + mi*16)*QLD + ks*16, QLD);
                #pragma unroll
                for (int ni = 0; ni < 2; ni++)
                    wmma::load_matrix_sync(bf[ni], Vs + (ks*16)*QLD + wn*32 + ni*16, QLD);
                #pragma unroll
                for (int mi = 0; mi < 2; mi++)
                    #pragma unroll
                    for (int ni = 0; ni < 2; ni++)
                        wmma::mma_sync(pacc[mi][ni], af[mi], bf[ni], pacc[mi][ni]);
            }
            #pragma unroll
            for (int mi = 0; mi < 2; mi++)
                #pragma unroll
                for (int ni = 0; ni < 2; ni++)
                    wmma::store_matrix_sync(Ss + (wm*32 + mi*16)*SLD + wn*32 + ni*16,
                                            pacc[mi][ni], SLD, wmma::mem_row_major);
        }
        __syncthreads();

        // O = O*alpha + PV
        #pragma unroll
        for (int e = 0; e < 32; e++) {
            int i = tid + e*256;
            int r = i >> 6, c = i & 63;
            Os[r*SLD + c] = Os[r*SLD + c]*al[r] + Ss[r*SLD + c];
        }
        __syncthreads();
    }

    // write O / l  -> g_o[B,T,H*D]
    #pragma unroll
    for (int e = 0; e < 32; e++) {
        int i = tid + e*256;
        int r = i >> 6, c = i & 63;
        int t = qi*AQ + r;
        float val = Os[r*SLD + c] / l_s[r];
        g_o[((size_t)(b*SEQ + t))*DMODEL + h*DHEAD + c] = __float2bfloat16(val);
    }
}

// ---------------- launcher ----------------
extern "C" void kernel_launch(void* const* d_in, const int* in_sizes, int n_in,
                              void* d_out, int out_size)
{
    const float* x     = (const float*)d_in[0];
    const float* Wq    = (const float*)d_in[1];
    const float* Wk    = (const float*)d_in[2];
    const float* Wv    = (const float*)d_in[3];
    const float* Wo    = (const float*)d_in[4];
    const float* bo    = (const float*)d_in[5];
    const float* gamma = (const float*)d_in[6];
    const float* beta  = (const float*)d_in[7];
    float* out = (float*)d_out;

    cudaFuncSetAttribute(gemm_kernel, cudaFuncAttributeMaxDynamicSharedMemorySize, GEMM_SMEM);
    cudaFuncSetAttribute(attn_kernel, cudaFuncAttributeMaxDynamicSharedMemorySize, ATTN_SMEM);

    ln_kernel<<<MTOK, 256>>>(x, gamma, beta);

    dim3 gg(DMODEL/BN, MTOK/BM);   // (8, 32)
    gemm_kernel<<<gg, 256, GEMM_SMEM>>>(Wq, nullptr, nullptr, 0);
    gemm_kernel<<<gg, 256, GEMM_SMEM>>>(Wk, nullptr, nullptr, 1);
    gemm_kernel<<<gg, 256, GEMM_SMEM>>>(Wv, nullptr, nullptr, 2);

    dim3 ag(SEQ/AQ, NHEAD, BATCH); // (16, 16, 2)
    attn_kernel<<<ag, 256, ATTN_SMEM>>>();

    gemm_kernel<<<gg, 256, GEMM_SMEM>>>(Wo, bo, out, 3);
}

// round 3
// speedup vs baseline: 3.7613x; 3.7613x over previous
#include <cuda_runtime.h>
#include <cuda_bf16.h>
#include <mma.h>
#include <cstdint>

using namespace nvcuda;
typedef unsigned int u32;

#define BATCH 2
#define SEQ   2048
#define DMODEL 1024
#define NHEAD 16
#define DHEAD 64
#define MTOK  (BATCH*SEQ)
#define EPS   1e-5f

// ---------------- static device scratch ----------------
__device__ float          g_xn [MTOK*DMODEL];
__device__ __nv_bfloat16  g_xnb[MTOK*DMODEL];
__device__ __nv_bfloat16  g_wb [4][DMODEL*DMODEL];   // bf16 weights: q,k,v,o
__device__ __nv_bfloat16  g_q  [MTOK*DMODEL];        // [B,H,T,D]
__device__ __nv_bfloat16  g_k  [MTOK*DMODEL];
__device__ __nv_bfloat16  g_v  [MTOK*DMODEL];
__device__ __nv_bfloat16  g_o  [MTOK*DMODEL];        // [B,T,H*D]

// ---------------- cp.async helpers ----------------
__device__ __forceinline__ void cpa16(void* s, const void* g) {
    u32 sa = (u32)__cvta_generic_to_shared(s);
    asm volatile("cp.async.cg.shared.global [%0], [%1], 16;\n" :: "r"(sa), "l"(g));
}
__device__ __forceinline__ void cpa_commit() { asm volatile("cp.async.commit_group;\n"); }
template<int N> __device__ __forceinline__ void cpa_wait() {
    asm volatile("cp.async.wait_group %0;\n" :: "n"(N));
}

__device__ __forceinline__ u32 packbf2(float a, float b) {
    __nv_bfloat162 t = __floats2bfloat162_rn(a, b);
    return *(u32*)&t;
}

__device__ __forceinline__ void mma16816(float* c, const u32* a, u32 b0, u32 b1) {
    asm volatile("mma.sync.aligned.m16n8k16.row.col.f32.bf16.bf16.f32 "
        "{%0,%1,%2,%3}, {%4,%5,%6,%7}, {%8,%9}, {%0,%1,%2,%3};\n"
        : "+f"(c[0]), "+f"(c[1]), "+f"(c[2]), "+f"(c[3])
        : "r"(a[0]), "r"(a[1]), "r"(a[2]), "r"(a[3]), "r"(b0), "r"(b1));
}

// ---------------- LayerNorm ----------------
__global__ __launch_bounds__(256)
void ln_kernel(const float* __restrict__ x,
               const float* __restrict__ gamma,
               const float* __restrict__ beta)
{
    __shared__ float red1[8], red2[8];
    __shared__ float s_mean, s_rstd;
    const int row = blockIdx.x;
    const int tid = threadIdx.x;

    float4 v = ((const float4*)(x + (size_t)row*DMODEL))[tid];
    float s1 = v.x + v.y + v.z + v.w;
    float s2 = v.x*v.x + v.y*v.y + v.z*v.z + v.w*v.w;
    #pragma unroll
    for (int o = 16; o > 0; o >>= 1) {
        s1 += __shfl_xor_sync(0xffffffffu, s1, o);
        s2 += __shfl_xor_sync(0xffffffffu, s2, o);
    }
    if ((tid & 31) == 0) { red1[tid >> 5] = s1; red2[tid >> 5] = s2; }
    __syncthreads();
    if (tid == 0) {
        float t1 = 0.f, t2 = 0.f;
        #pragma unroll
        for (int i = 0; i < 8; i++) { t1 += red1[i]; t2 += red2[i]; }
        float mean = t1 * (1.f/DMODEL);
        float var  = t2 * (1.f/DMODEL) - mean*mean;
        s_mean = mean;
        s_rstd = rsqrtf(var + EPS);
    }
    __syncthreads();
    const float mean = s_mean, rstd = s_rstd;

    float4 g  = ((const float4*)gamma)[tid];
    float4 bt = ((const float4*)beta )[tid];
    float4 o;
    o.x = (v.x - mean)*rstd*g.x + bt.x;
    o.y = (v.y - mean)*rstd*g.y + bt.y;
    o.z = (v.z - mean)*rstd*g.z + bt.z;
    o.w = (v.w - mean)*rstd*g.w + bt.w;
    ((float4*)(g_xn + (size_t)row*DMODEL))[tid] = o;
    __nv_bfloat162* dst = (__nv_bfloat162*)(g_xnb + (size_t)row*DMODEL);
    dst[2*tid]   = __floats2bfloat162_rn(o.x, o.y);
    dst[2*tid+1] = __floats2bfloat162_rn(o.z, o.w);
}

// ---------------- weight fp32 -> bf16 (once per launch) ----------------
__global__ __launch_bounds__(256)
void convw_kernel(const float* __restrict__ Wq, const float* __restrict__ Wk,
                  const float* __restrict__ Wv, const float* __restrict__ Wo)
{
    const float* src = (blockIdx.y == 0) ? Wq : (blockIdx.y == 1) ? Wk :
                       (blockIdx.y == 2) ? Wv : Wo;
    __nv_bfloat162* dst = (__nv_bfloat162*)g_wb[blockIdx.y];
    int i = blockIdx.x*256 + threadIdx.x;     // one float4 each
    float4 v = ((const float4*)src)[i];
    dst[2*i]   = __floats2bfloat162_rn(v.x, v.y);
    dst[2*i+1] = __floats2bfloat162_rn(v.z, v.w);
}

// ---------------- GEMM: [4096,1024] @ [1024,1024], 3-stage cp.async ----------------
#define BM 128
#define BN 128
#define BK 32
#define LDA 40
#define LDB 136
#define LDS 132
#define NSTG 3
#define GEMM_SMEM_PIPE (NSTG*(BM*LDA + BK*LDB)*2)
#define GEMM_SMEM_EPI  (BM*LDS*4)
#define GEMM_SMEM (GEMM_SMEM_EPI > GEMM_SMEM_PIPE ? GEMM_SMEM_EPI : GEMM_SMEM_PIPE)

__global__ __launch_bounds__(256)
void gemm_kernel(const float* __restrict__ bias, float* __restrict__ outf, int mode_base)
{
    extern __shared__ char smem_raw[];
    __nv_bfloat16* As = (__nv_bfloat16*)smem_raw;           // NSTG x [BM][LDA]
    __nv_bfloat16* Bs = As + NSTG*BM*LDA;                   // NSTG x [BK][LDB]
    float* stage = (float*)smem_raw;                        // epilogue [BM][LDS]

    const int mode = mode_base + blockIdx.z;
    const __nv_bfloat16* A  = (mode == 3) ? g_o : g_xnb;
    const __nv_bfloat16* Bw = g_wb[mode];
    __nv_bfloat16* outb = (mode == 0) ? g_q : (mode == 1) ? g_k :
                          (mode == 2) ? g_v : nullptr;

    const int tid = threadIdx.x;
    const int w = tid >> 5;
    const int wm = w >> 1, wn = w & 1;
    const int bn = blockIdx.x, bm = blockIdx.y;

    auto prefetch = [&](int kt, int st) {
        __nv_bfloat16* As_s = As + st*BM*LDA;
        __nv_bfloat16* Bs_s = Bs + st*BK*LDB;
        #pragma unroll
        for (int l = 0; l < 2; l++) {                       // A: 128x32 -> 512 chunks
            int i = tid + l*256;
            int r = i >> 2, c = i & 3;
            cpa16(As_s + r*LDA + c*8,
                  A + (size_t)(bm*BM + r)*DMODEL + kt*BK + c*8);
        }
        #pragma unroll
        for (int l = 0; l < 2; l++) {                       // B: 32x128 -> 512 chunks
            int i = tid + l*256;
            int r = i >> 4, c = i & 15;
            cpa16(Bs_s + r*LDB + c*8,
                  Bw + (size_t)(kt*BK + r)*DMODEL + bn*BN + c*8);
        }
    };

    wmma::fragment<wmma::accumulator,16,16,16,float> acc[2][4];
    #pragma unroll
    for (int i = 0; i < 2; i++)
        #pragma unroll
        for (int j = 0; j < 4; j++) wmma::fill_fragment(acc[i][j], 0.0f);

    prefetch(0, 0); cpa_commit();
    prefetch(1, 1); cpa_commit();

    const int NT = DMODEL / BK;   // 32
    for (int kt = 0; kt < NT; kt++) {
        cpa_wait<1>();
        __syncthreads();
        const int st = kt % NSTG;
        __nv_bfloat16* As_s = As + st*BM*LDA;
        __nv_bfloat16* Bs_s = Bs + st*BK*LDB;
        #pragma unroll
        for (int ks = 0; ks < BK; ks += 16) {
            wmma::fragment<wmma::matrix_a,16,16,16,__nv_bfloat16,wmma::row_major> af[2];
            wmma::fragment<wmma::matrix_b,16,16,16,__nv_bfloat16,wmma::row_major> bf[4];
            #pragma unroll
            for (int mi = 0; mi < 2; mi++)
                wmma::load_matrix_sync(af[mi], As_s + (wm*32 + mi*16)*LDA + ks, LDA);
            #pragma unroll
            for (int ni = 0; ni < 4; ni++)
                wmma::load_matrix_sync(bf[ni], Bs_s + ks*LDB + wn*64 + ni*16, LDB);
            #pragma unroll
            for (int mi = 0; mi < 2; mi++)
                #pragma unroll
                for (int ni = 0; ni < 4; ni++)
                    wmma::mma_sync(acc[mi][ni], af[mi], bf[ni], acc[mi][ni]);
        }
        __syncthreads();
        if (kt + 2 < NT) prefetch(kt + 2, (kt + 2) % NSTG);
        cpa_commit();
    }

    #pragma unroll
    for (int mi = 0; mi < 2; mi++)
        #pragma unroll
        for (int ni = 0; ni < 4; ni++)
            wmma::store_matrix_sync(stage + (wm*32 + mi*16)*LDS + wn*64 + ni*16,
                                    acc[mi][ni], LDS, wmma::mem_row_major);
    __syncthreads();

    if (mode == 3) {
        #pragma unroll 8
        for (int e = 0; e < 64; e++) {
            int idx = tid + e*256;
            int r = idx >> 7, c = idx & 127;
            int m = bm*BM + r, n = bn*BN + c;
            outf[(size_t)m*DMODEL + n] =
                stage[r*LDS + c] + bias[n] + g_xn[(size_t)m*DMODEL + n];
        }
    } else {
        #pragma unroll 8
        for (int e = 0; e < 64; e++) {
            int idx = tid + e*256;
            int r = idx >> 7, c = idx & 127;
            int m = bm*BM + r, n = bn*BN + c;
            int b = m >> 11, t = m & 2047;
            int h = n >> 6,  d = n & 63;
            outb[(((size_t)(b*NHEAD + h))*SEQ + t)*DHEAD + d] =
                __float2bfloat16(stage[r*LDS + c]);
        }
    }
}

// ---------------- Flash attention (register-resident FA2) ----------------
// 8 warps, warp w owns query rows [w*16, w*16+16). 128 q-rows/block, 64 kv/iter.
#define AQ 128
#define AK 64
#define KP 72
#define ATTN_SMEM ((AQ*KP + 2*AK*KP + 2*AK*KP)*2)

__global__ __launch_bounds__(256, 2)
void attn_kernel()
{
    extern __shared__ char smem_raw[];
    __nv_bfloat16* Qs = (__nv_bfloat16*)smem_raw;   // [128][72]
    __nv_bfloat16* Ks = Qs + AQ*KP;                 // 2 x [64][72]
    __nv_bfloat16* Vs = Ks + 2*AK*KP;               // 2 x [64][72]

    const int tid  = threadIdx.x;
    const int w    = tid >> 5;
    const int lane = tid & 31;
    const int qi = (int)gridDim.x - 1 - (int)blockIdx.x;   // heavy tiles first
    const int h  = blockIdx.y, b = blockIdx.z;
    const size_t head_base = ((size_t)(b*NHEAD + h))*SEQ*DHEAD;
    const __nv_bfloat16* Kg = g_k + head_base;
    const __nv_bfloat16* Vg = g_v + head_base;

    const int numj = 2*qi + 2;

    // group 0: Q tile + KV tile 0
    {
        const __nv_bfloat16* qptr = g_q + head_base + (size_t)qi*AQ*DHEAD;
        #pragma unroll
        for (int l = 0; l < 4; l++) {
            int i = tid + l*256;
            int r = i >> 3, c = i & 7;
            cpa16(Qs + r*KP + c*8, qptr + r*DHEAD + c*8);
        }
        #pragma unroll
        for (int l = 0; l < 2; l++) {
            int i = tid + l*256;
            int r = i >> 3, c = i & 7;
            cpa16(Ks + r*KP + c*8, Kg + r*DHEAD + c*8);
            cpa16(Vs + r*KP + c*8, Vg + r*DHEAD + c*8);
        }
        cpa_commit();
    }
    // group 1: KV tile 1 (or empty)
    if (numj > 1) {
        #pragma unroll
        for (int l = 0; l < 2; l++) {
            int i = tid + l*256;
            int r = i >> 3, c = i & 7;
            cpa16(Ks + AK*KP + r*KP + c*8, Kg + (size_t)(AK + r)*DHEAD + c*8);
            cpa16(Vs + AK*KP + r*KP + c*8, Vg + (size_t)(AK + r)*DHEAD + c*8);
        }
    }
    cpa_commit();

    const int rq = lane >> 2;        // row within 8-group
    const int qd = lane & 3;         // quad position (col pair)
    const int row0 = qi*AQ + w*16 + rq;   // global query row (and row0+8)

    u32 qa[4][4];                    // Q A-frags per k-step
    float o[8][4];
    #pragma unroll
    for (int nd = 0; nd < 8; nd++)
        #pragma unroll
        for (int e = 0; e < 4; e++) o[nd][e] = 0.f;
    float mrun0 = -INFINITY, mrun1 = -INFINITY, lrun0 = 0.f, lrun1 = 0.f;

    const int mid = lane >> 3, rr = lane & 7;   // ldmatrix addressing roles

    for (int j = 0; j < numj; j++) {
        cpa_wait<1>();
        __syncthreads();

        if (j == 0) {
            #pragma unroll
            for (int kk = 0; kk < 4; kk++) {
                u32 addr = (u32)__cvta_generic_to_shared(
                    Qs + (w*16 + (mid & 1)*8 + rr)*KP + kk*16 + (mid & 2)*4);
                asm volatile("ldmatrix.sync.aligned.m8n8.x4.shared.b16 {%0,%1,%2,%3}, [%4];\n"
                    : "=r"(qa[kk][0]), "=r"(qa[kk][1]), "=r"(qa[kk][2]), "=r"(qa[kk][3])
                    : "r"(addr));
            }
        }

        const int colbase = j*AK;
        const bool active = colbase <= qi*AQ + w*16 + 15;
        __nv_bfloat16* Kt = Ks + (j & 1)*AK*KP;
        __nv_bfloat16* Vt = Vs + (j & 1)*AK*KP;

        if (active) {
            float c[8][4];
            #pragma unroll
            for (int nf = 0; nf < 8; nf++)
                #pragma unroll
                for (int e = 0; e < 4; e++) c[nf][e] = 0.f;

            // ---- S = Q K^T ----
            #pragma unroll
            for (int kk = 0; kk < 4; kk++) {
                #pragma unroll
                for (int np = 0; np < 4; np++) {     // n-tile pair {2np, 2np+1}
                    u32 b0, b1, b2, b3;
                    u32 addr = (u32)__cvta_generic_to_shared(
                        Kt + (np*16 + (mid & 2)*4 + rr)*KP + kk*16 + (mid & 1)*8);
                    asm volatile("ldmatrix.sync.aligned.m8n8.x4.shared.b16 {%0,%1,%2,%3}, [%4];\n"
                        : "=r"(b0), "=r"(b1), "=r"(b2), "=r"(b3) : "r"(addr));
                    mma16816(c[2*np],   qa[kk], b0, b1);
                    mma16816(c[2*np+1], qa[kk], b2, b3);
                }
            }

            // ---- softmax (registers + quad shfl) ----
            const bool needmask = (colbase + AK - 1) > (qi*AQ + w*16);
            float tm0 = -INFINITY, tm1 = -INFINITY;
            #pragma unroll
            for (int nf = 0; nf < 8; nf++) {
                int cg = colbase + nf*8 + qd*2;
                float s0 = c[nf][0]*0.125f, s1 = c[nf][1]*0.125f;
                float s2 = c[nf][2]*0.125f, s3 = c[nf][3]*0.125f;
                if (needmask) {
                    if (cg     > row0    ) s0 = -INFINITY;
                    if (cg + 1 > row0    ) s1 = -INFINITY;
                    if (cg     > row0 + 8) s2 = -INFINITY;
                    if (cg + 1 > row0 + 8) s3 = -INFINITY;
                }
                c[nf][0] = s0; c[nf][1] = s1; c[nf][2] = s2; c[nf][3] = s3;
                tm0 = fmaxf(tm0, fmaxf(s0, s1));
                tm1 = fmaxf(tm1, fmaxf(s2, s3));
            }
            tm0 = fmaxf(tm0, __shfl_xor_sync(0xffffffffu, tm0, 1));
            tm0 = fmaxf(tm0, __shfl_xor_sync(0xffffffffu, tm0, 2));
            tm1 = fmaxf(tm1, __shfl_xor_sync(0xffffffffu, tm1, 1));
            tm1 = fmaxf(tm1, __shfl_xor_sync(0xffffffffu, tm1, 2));

            float mnew0 = fmaxf(mrun0, tm0), mnew1 = fmaxf(mrun1, tm1);
            float alpha0 = __expf(mrun0 - mnew0), alpha1 = __expf(mrun1 - mnew1);
            float sum0 = 0.f, sum1 = 0.f;
            u32 pa[4][4];
            #pragma unroll
            for (int nf = 0; nf < 8; nf++) {
                float p0 = __expf(c[nf][0] - mnew0);
                float p1 = __expf(c[nf][1] - mnew0);
                float p2 = __expf(c[nf][2] - mnew1);
                float p3 = __expf(c[nf][3] - mnew1);
                sum0 += p0 + p1; sum1 += p2 + p3;
                u32 lo = packbf2(p0, p1), hi = packbf2(p2, p3);
                int kk = nf >> 1;
                if ((nf & 1) == 0) { pa[kk][0] = lo; pa[kk][1] = hi; }
                else               { pa[kk][2] = lo; pa[kk][3] = hi; }
            }
            sum0 += __shfl_xor_sync(0xffffffffu, sum0, 1);
            sum0 += __shfl_xor_sync(0xffffffffu, sum0, 2);
            sum1 += __shfl_xor_sync(0xffffffffu, sum1, 1);
            sum1 += __shfl_xor_sync(0xffffffffu, sum1, 2);
            lrun0 = lrun0*alpha0 + sum0;
            lrun1 = lrun1*alpha1 + sum1;
            mrun0 = mnew0; mrun1 = mnew1;

            #pragma unroll
            for (int nd = 0; nd < 8; nd++) {
                o[nd][0] *= alpha0; o[nd][1] *= alpha0;
                o[nd][2] *= alpha1; o[nd][3] *= alpha1;
            }

            // ---- O += P V ----
            #pragma unroll
            for (int kk = 0; kk < 4; kk++) {
                #pragma unroll
                for (int np = 0; np < 4; np++) {     // d-tile pair {2np, 2np+1}
                    u32 v0, v1, v2, v3;
                    u32 addr = (u32)__cvta_generic_to_shared(
                        Vt + (kk*16 + (mid & 1)*8 + rr)*KP + np*16 + (mid & 2)*4);
                    asm volatile("ldmatrix.sync.aligned.m8n8.x4.trans.shared.b16 {%0,%1,%2,%3}, [%4];\n"
                        : "=r"(v0), "=r"(v1), "=r"(v2), "=r"(v3) : "r"(addr));
                    mma16816(o[2*np],   pa[kk], v0, v1);
                    mma16816(o[2*np+1], pa[kk], v2, v3);
                }
            }
        }

        __syncthreads();
        if (j + 2 < numj) {
            const size_t kbase = (size_t)(j + 2)*AK;
            __nv_bfloat16* Kd = Ks + (j & 1)*AK*KP;
            __nv_bfloat16* Vd = Vs + (j & 1)*AK*KP;
            #pragma unroll
            for (int l = 0; l < 2; l++) {
                int i = tid + l*256;
                int r = i >> 3, c = i & 7;
                cpa16(Kd + r*KP + c*8, Kg + (kbase + r)*DHEAD + c*8);
                cpa16(Vd + r*KP + c*8, Vg + (kbase + r)*DHEAD + c*8);
            }
        }
        cpa_commit();
    }

    // ---- write O / l ----
    float inv0 = 1.f / lrun0, inv1 = 1.f / lrun1;
    __nv_bfloat16* op = g_o + ((size_t)(b*SEQ) + (size_t)qi*AQ)*DMODEL + h*DHEAD;
    const int r0 = w*16 + rq;
    #pragma unroll
    for (int nd = 0; nd < 8; nd++) {
        int cidx = nd*8 + qd*2;
        *(__nv_bfloat162*)(op + (size_t)r0*DMODEL + cidx) =
            __floats2bfloat162_rn(o[nd][0]*inv0, o[nd][1]*inv0);
        *(__nv_bfloat162*)(op + (size_t)(r0+8)*DMODEL + cidx) =
            __floats2bfloat162_rn(o[nd][2]*inv1, o[nd][3]*inv1);
    }
}

// ---------------- launcher ----------------
extern "C" void kernel_launch(void* const* d_in, const int* in_sizes, int n_in,
                              void* d_out, int out_size)
{
    const float* x     = (const float*)d_in[0];
    const float* Wq    = (const float*)d_in[1];
    const float* Wk    = (const float*)d_in[2];
    const float* Wv    = (const float*)d_in[3];
    const float* Wo    = (const float*)d_in[4];
    const float* bo    = (const float*)d_in[5];
    const float* gamma = (const float*)d_in[6];
    const float* beta  = (const float*)d_in[7];
    float* out = (float*)d_out;

    cudaFuncSetAttribute(gemm_kernel, cudaFuncAttributeMaxDynamicSharedMemorySize, GEMM_SMEM);
    cudaFuncSetAttribute(attn_kernel, cudaFuncAttributeMaxDynamicSharedMemorySize, ATTN_SMEM);

    ln_kernel<<<MTOK, 256>>>(x, gamma, beta);
    convw_kernel<<<dim3(DMODEL*DMODEL/1024, 4), 256>>>(Wq, Wk, Wv, Wo);

    dim3 gqkv(DMODEL/BN, MTOK/BM, 3);     // (8, 32, 3)
    gemm_kernel<<<gqkv, 256, GEMM_SMEM>>>(nullptr, nullptr, 0);

    dim3 ag(SEQ/AQ, NHEAD, BATCH);        // (16, 16, 2)
    attn_kernel<<<ag, 256, ATTN_SMEM>>>();

    dim3 go(DMODEL/BN, MTOK/BM, 1);
    gemm_kernel<<<go, 256, GEMM_SMEM>>>(bo, out, 3);
}

// round 4
// speedup vs baseline: 5.4026x; 1.4364x over previous
#include <cuda_runtime.h>
#include <cuda_bf16.h>
#include <cstdint>

typedef unsigned int u32;

#define BATCH 2
#define SEQ   2048
#define DMODEL 1024
#define NHEAD 16
#define DHEAD 64
#define MTOK  (BATCH*SEQ)
#define EPS   1e-5f
#define QSCALE (0.125f*1.44269504f)

__device__ float          g_xn [MTOK*DMODEL];
__device__ __nv_bfloat16  g_xnb[MTOK*DMODEL];
__device__ __nv_bfloat16  g_wb [4][DMODEL*DMODEL];
__device__ __nv_bfloat16  g_q  [MTOK*DMODEL];
__device__ __nv_bfloat16  g_k  [MTOK*DMODEL];
__device__ __nv_bfloat16  g_v  [MTOK*DMODEL];
__device__ __nv_bfloat16  g_o  [MTOK*DMODEL];

__device__ __forceinline__ void cpa16(void* s, const void* g) {
    u32 sa = (u32)__cvta_generic_to_shared(s);
    asm volatile("cp.async.cg.shared.global [%0], [%1], 16;\n" :: "r"(sa), "l"(g));
}
__device__ __forceinline__ void cpa_commit() { asm volatile("cp.async.commit_group;\n"); }
template<int N> __device__ __forceinline__ void cpa_wait() {
    asm volatile("cp.async.wait_group %0;\n" :: "n"(N));
}
__device__ __forceinline__ u32 packbf2(float a, float b) {
    __nv_bfloat162 t = __floats2bfloat162_rn(a, b);
    return *(u32*)&t;
}
__device__ __forceinline__ void mma16816(float* c, const u32* a, u32 b0, u32 b1) {
    asm volatile("mma.sync.aligned.m16n8k16.row.col.f32.bf16.bf16.f32 "
        "{%0,%1,%2,%3}, {%4,%5,%6,%7}, {%8,%9}, {%0,%1,%2,%3};\n"
        : "+f"(c[0]), "+f"(c[1]), "+f"(c[2]), "+f"(c[3])
        : "r"(a[0]), "r"(a[1]), "r"(a[2]), "r"(a[3]), "r"(b0), "r"(b1));
}
__device__ __forceinline__ void ldsm4(u32* d, const __nv_bfloat16* p) {
    u32 addr = (u32)__cvta_generic_to_shared(p);
    asm volatile("ldmatrix.sync.aligned.m8n8.x4.shared.b16 {%0,%1,%2,%3}, [%4];\n"
        : "=r"(d[0]), "=r"(d[1]), "=r"(d[2]), "=r"(d[3]) : "r"(addr));
}
__device__ __forceinline__ void ldsm4t(u32& d0, u32& d1, u32& d2, u32& d3, const __nv_bfloat16* p) {
    u32 addr = (u32)__cvta_generic_to_shared(p);
    asm volatile("ldmatrix.sync.aligned.m8n8.x4.trans.shared.b16 {%0,%1,%2,%3}, [%4];\n"
        : "=r"(d0), "=r"(d1), "=r"(d2), "=r"(d3) : "r"(addr));
}

__global__ __launch_bounds__(256)
void ln_kernel(const float* __restrict__ x,
               const float* __restrict__ gamma,
               const float* __restrict__ beta)
{
    __shared__ float red1[8], red2[8];
    __shared__ float s_mean, s_rstd;
    const int row = blockIdx.x;
    const int tid = threadIdx.x;

    float4 v = ((const float4*)(x + (size_t)row*DMODEL))[tid];
    float s1 = v.x + v.y + v.z + v.w;
    float s2 = v.x*v.x + v.y*v.y + v.z*v.z + v.w*v.w;
    #pragma unroll
    for (int o = 16; o > 0; o >>= 1) {
        s1 += __shfl_xor_sync(0xffffffffu, s1, o);
        s2 += __shfl_xor_sync(0xffffffffu, s2, o);
    }
    if ((tid & 31) == 0) { red1[tid >> 5] = s1; red2[tid >> 5] = s2; }
    __syncthreads();
    if (tid == 0) {
        float t1 = 0.f, t2 = 0.f;
        #pragma unroll
        for (int i = 0; i < 8; i++) { t1 += red1[i]; t2 += red2[i]; }
        float mean = t1 * (1.f/DMODEL);
        float var  = t2 * (1.f/DMODEL) - mean*mean;
        s_mean = mean;
        s_rstd = rsqrtf(var + EPS);
    }
    __syncthreads();
    const float mean = s_mean, rstd = s_rstd;

    float4 g  = ((const float4*)gamma)[tid];
    float4 bt = ((const float4*)beta )[tid];
    float4 o;
    o.x = (v.x - mean)*rstd*g.x + bt.x;
    o.y = (v.y - mean)*rstd*g.y + bt.y;
    o.z = (v.z - mean)*rstd*g.z + bt.z;
    o.w = (v.w - mean)*rstd*g.w + bt.w;
    ((float4*)(g_xn + (size_t)row*DMODEL))[tid] = o;
    __nv_bfloat162* dst = (__nv_bfloat162*)(g_xnb + (size_t)row*DMODEL);
    dst[2*tid]   = __floats2bfloat162_rn(o.x, o.y);
    dst[2*tid+1] = __floats2bfloat162_rn(o.z, o.w);
}

__global__ __launch_bounds__(256)
void convw_kernel(const float* __restrict__ Wq, const float* __restrict__ Wk,
                  const float* __restrict__ Wv, const float* __restrict__ Wo)
{
    const float* src = (blockIdx.y == 0) ? Wq : (blockIdx.y == 1) ? Wk :
                       (blockIdx.y == 2) ? Wv : Wo;
    __nv_bfloat162* dst = (__nv_bfloat162*)g_wb[blockIdx.y];
    int i = blockIdx.x*256 + threadIdx.x;
    float4 v = ((const float4*)src)[i];
    dst[2*i]   = __floats2bfloat162_rn(v.x, v.y);
    dst[2*i+1] = __floats2bfloat162_rn(v.z, v.w);
}

#define BM 128
#define BN 128
#define BK 32
#define LDA 40
#define LDB 136
#define NSTG 4
#define GEMM_SMEM (NSTG*(BM*LDA + BK*LDB)*2)

__global__ __launch_bounds__(128)
void gemm_kernel(const float* __restrict__ bias, float* __restrict__ outf, int mode_base)
{
    extern __shared__ char smem_raw[];
    __nv_bfloat16* As = (__nv_bfloat16*)smem_raw;
    __nv_bfloat16* Bs = As + NSTG*BM*LDA;

    const int mode = mode_base + blockIdx.z;
    const __nv_bfloat16* A  = (mode == 3) ? g_o : g_xnb;
    const __nv_bfloat16* Bw = g_wb[mode];
    __nv_bfloat16* outb = (mode == 0) ? g_q : (mode == 1) ? g_k :
                          (mode == 2) ? g_v : nullptr;

    const int tid  = threadIdx.x;
    const int w    = tid >> 5;
    const int lane = tid & 31;
    const int wm = w >> 1, wn = w & 1;
    const int bn = blockIdx.x, bm = blockIdx.y;
    const int mid = lane >> 3, rr = lane & 7;
    const int rq = lane >> 2, qd = lane & 3;

    auto prefetch = [&](int kt, int st) {
        __nv_bfloat16* As_s = As + st*BM*LDA;
        __nv_bfloat16* Bs_s = Bs + st*BK*LDB;
        #pragma unroll
        for (int l = 0; l < 4; l++) {
            int i = tid + l*128;
            int r = i >> 2, c = i & 3;
            cpa16(As_s + r*LDA + c*8,
                  A + (size_t)(bm*BM + r)*DMODEL + kt*BK + c*8);
        }
        #pragma unroll
        for (int l = 0; l < 4; l++) {
            int i = tid + l*128;
            int r = i >> 4, c = i & 15;
            cpa16(Bs_s + r*LDB + c*8,
                  Bw + (size_t)(kt*BK + r)*DMODEL + bn*BN + c*8);
        }
    };

    float acc[4][8][4];
    #pragma unroll
    for (int mi = 0; mi < 4; mi++)
        #pragma unroll
        for (int nf = 0; nf < 8; nf++)
            #pragma unroll
            for (int e = 0; e < 4; e++) acc[mi][nf][e] = 0.f;

    prefetch(0, 0); cpa_commit();
    prefetch(1, 1); cpa_commit();
    prefetch(2, 2); cpa_commit();

    const int NT = DMODEL / BK;
    for (int kt = 0; kt < NT; kt++) {
        cpa_wait<2>();
        __syncthreads();
        const int st = kt & 3;
        __nv_bfloat16* As_s = As + st*BM*LDA;
        __nv_bfloat16* Bs_s = Bs + st*BK*LDB;
        #pragma unroll
        for (int kk = 0; kk < 2; kk++) {
            u32 a[4][4];
            #pragma unroll
            for (int mi = 0; mi < 4; mi++)
                ldsm4(a[mi], As_s + (wm*64 + mi*16 + (mid & 1)*8 + rr)*LDA
                             + kk*16 + (mid & 2)*4);
            #pragma unroll
            for (int nt = 0; nt < 4; nt++) {
                u32 b0, b1, b2, b3;
                ldsm4t(b0, b1, b2, b3,
                       Bs_s + (kk*16 + (mid & 1)*8 + rr)*LDB
                       + wn*64 + nt*16 + (mid & 2)*4);
                #pragma unroll
                for (int mi = 0; mi < 4; mi++) {
                    mma16816(acc[mi][2*nt],   a[mi], b0, b1);
                    mma16816(acc[mi][2*nt+1], a[mi], b2, b3);
                }
            }
        }
        if (kt + 3 < NT) prefetch(kt + 3, (kt + 3) & 3);
        cpa_commit();
    }

    if (mode == 3) {
        #pragma unroll
        for (int mi = 0; mi < 4; mi++) {
            int r0 = bm*BM + wm*64 + mi*16 + rq;
            #pragma unroll
            for (int nf = 0; nf < 8; nf++) {
                int c0 = bn*BN + wn*64 + nf*8 + qd*2;
                float b0 = bias[c0], b1 = bias[c0+1];
                float2 x0 = *(const float2*)(g_xn + (size_t)r0*DMODEL + c0);
                float2 x1 = *(const float2*)(g_xn + (size_t)(r0+8)*DMODEL + c0);
                float2 o0 = { acc[mi][nf][0] + b0 + x0.x, acc[mi][nf][1] + b1 + x0.y };
                float2 o1 = { acc[mi][nf][2] + b0 + x1.x, acc[mi][nf][3] + b1 + x1.y };
                *(float2*)(outf + (size_t)r0*DMODEL + c0)     = o0;
                *(float2*)(outf + (size_t)(r0+8)*DMODEL + c0) = o1;
            }
        }
    } else {
        const float scale = (mode == 0) ? QSCALE : 1.0f;
        #pragma unroll
        for (int mi = 0; mi < 4; mi++) {
            int m0 = bm*BM + wm*64 + mi*16 + rq;
            int b0i = m0 >> 11, t0 = m0 & 2047;
            int b1i = (m0+8) >> 11, t1 = (m0+8) & 2047;
            #pragma unroll
            for (int nf = 0; nf < 8; nf++) {
                int n = bn*BN + wn*64 + nf*8 + qd*2;
                int h = n >> 6, d = n & 63;
                *(__nv_bfloat162*)(outb + (((size_t)(b0i*NHEAD + h))*SEQ + t0)*DHEAD + d) =
                    __floats2bfloat162_rn(acc[mi][nf][0]*scale, acc[mi][nf][1]*scale);
                *(__nv_bfloat162*)(outb + (((size_t)(b1i*NHEAD + h))*SEQ + t1)*DHEAD + d) =
                    __floats2bfloat162_rn(acc[mi][nf][2]*scale, acc[mi][nf][3]*scale);
            }
        }
    }
}

#define AQ 128
#define AK 64
#define KP 72
#define ATTN_SMEM ((AQ*KP + 2*AK*KP + 2*AK*KP)*2)

__global__ __launch_bounds__(256, 2)
void attn_kernel()
{
    extern __shared__ char smem_raw[];
    __nv_bfloat16* Qs = (__nv_bfloat16*)smem_raw;
    __nv_bfloat16* Ks = Qs + AQ*KP;
    __nv_bfloat16* Vs = Ks + 2*AK*KP;

    const int tid  = threadIdx.x;
    const int w    = tid >> 5;
    const int lane = tid & 31;
    const int qi = (int)gridDim.x - 1 - (int)blockIdx.x;
    const int h  = blockIdx.y, b = blockIdx.z;
    const size_t head_base = ((size_t)(b*NHEAD + h))*SEQ*DHEAD;
    const __nv_bfloat16* Kg = g_k + head_base;
    const __nv_bfloat16* Vg = g_v + head_base;

    const int numj = 2*qi + 2;

    {
        const __nv_bfloat16* qptr = g_q + head_base + (size_t)qi*AQ*DHEAD;
        #pragma unroll
        for (int l = 0; l < 4; l++) {
            int i = tid + l*256;
            int r = i >> 3, c = i & 7;
            cpa16(Qs + r*KP + c*8, qptr + r*DHEAD + c*8);
        }
        #pragma unroll
        for (int l = 0; l < 2; l++) {
            int i = tid + l*256;
            int r = i >> 3, c = i & 7;
            cpa16(Ks + r*KP + c*8, Kg + r*DHEAD + c*8);
            cpa16(Vs + r*KP + c*8, Vg + r*DHEAD + c*8);
        }
        cpa_commit();
    }
    if (numj > 1) {
        #pragma unroll
        for (int l = 0; l < 2; l++) {
            int i = tid + l*256;
            int r = i >> 3, c = i & 7;
            cpa16(Ks + AK*KP + r*KP + c*8, Kg + (size_t)(AK + r)*DHEAD + c*8);
            cpa16(Vs + AK*KP + r*KP + c*8, Vg + (size_t)(AK + r)*DHEAD + c*8);
        }
    }
    cpa_commit();

    const int rq = lane >> 2;
    const int qd = lane & 3;
    const int row0 = qi*AQ + w*16 + rq;

    u32 qa[4][4];
    float o[8][4];
    #pragma unroll
    for (int nd = 0; nd < 8; nd++)
        #pragma unroll
        for (int e = 0; e < 4; e++) o[nd][e] = 0.f;
    float mrun0 = -INFINITY, mrun1 = -INFINITY, lrun0 = 0.f, lrun1 = 0.f;

    const int mid = lane >> 3, rr = lane & 7;

    for (int j = 0; j < numj; j++) {
        cpa_wait<1>();
        __syncthreads();

        if (j == 0) {
            #pragma unroll
            for (int kk = 0; kk < 4; kk++)
                ldsm4(qa[kk], Qs + (w*16 + (mid & 1)*8 + rr)*KP + kk*16 + (mid & 2)*4);
        }

        const int colbase = j*AK;
        const bool active = colbase <= qi*AQ + w*16 + 15;
        __nv_bfloat16* Kt = Ks + (j & 1)*AK*KP;
        __nv_bfloat16* Vt = Vs + (j & 1)*AK*KP;

        if (active) {
            float c[8][4];
            #pragma unroll
            for (int nf = 0; nf < 8; nf++)
                #pragma unroll
                for (int e = 0; e < 4; e++) c[nf][e] = 0.f;

            #pragma unroll
            for (int kk = 0; kk < 4; kk++) {
                #pragma unroll
                for (int np = 0; np < 4; np++) {
                    u32 b0, b1, b2, b3;
                    u32 addr = (u32)__cvta_generic_to_shared(
                        Kt + (np*16 + (mid & 2)*4 + rr)*KP + kk*16 + (mid & 1)*8);
                    asm volatile("ldmatrix.sync.aligned.m8n8.x4.shared.b16 {%0,%1,%2,%3}, [%4];\n"
                        : "=r"(b0), "=r"(b1), "=r"(b2), "=r"(b3) : "r"(addr));
                    mma16816(c[2*np],   qa[kk], b0, b1);
                    mma16816(c[2*np+1], qa[kk], b2, b3);
                }
            }

            const bool needmask = (colbase + AK - 1) > (qi*AQ + w*16);
            float tm0 = -INFINITY, tm1 = -INFINITY;
            #pragma unroll
            for (int nf = 0; nf < 8; nf++) {
                int cg = colbase + nf*8 + qd*2;
                float s0 = c[nf][0], s1 = c[nf][1];
                float s2 = c[nf][2], s3 = c[nf][3];
                if (needmask) {
                    if (cg     > row0    ) s0 = -INFINITY;
                    if (cg + 1 > row0    ) s1 = -INFINITY;
                    if (cg     > row0 + 8) s2 = -INFINITY;
                    if (cg + 1 > row0 + 8) s3 = -INFINITY;
                }
                c[nf][0] = s0; c[nf][1] = s1; c[nf][2] = s2; c[nf][3] = s3;
                tm0 = fmaxf(tm0, fmaxf(s0, s1));
                tm1 = fmaxf(tm1, fmaxf(s2, s3));
            }
            tm0 = fmaxf(tm0, __shfl_xor_sync(0xffffffffu, tm0, 1));
            tm0 = fmaxf(tm0, __shfl_xor_sync(0xffffffffu, tm0, 2));
            tm1 = fmaxf(tm1, __shfl_xor_sync(0xffffffffu, tm1, 1));
            tm1 = fmaxf(tm1, __shfl_xor_sync(0xffffffffu, tm1, 2));

            float mnew0 = fmaxf(mrun0, tm0), mnew1 = fmaxf(mrun1, tm1);
            float alpha0 = exp2f(mrun0 - mnew0), alpha1 = exp2f(mrun1 - mnew1);
            float sum0 = 0.f, sum1 = 0.f;
            u32 pa[4][4];
            #pragma unroll
            for (int nf = 0; nf < 8; nf++) {
                float p0 = exp2f(c[nf][0] - mnew0);
                float p1 = exp2f(c[nf][1] - mnew0);
                float p2 = exp2f(c[nf][2] - mnew1);
                float p3 = exp2f(c[nf][3] - mnew1);
                sum0 += p0 + p1; sum1 += p2 + p3;
                u32 lo = packbf2(p0, p1), hi = packbf2(p2, p3);
                int kk = nf >> 1;
                if ((nf & 1) == 0) { pa[kk][0] = lo; pa[kk][1] = hi; }
                else               { pa[kk][2] = lo; pa[kk][3] = hi; }
            }
            sum0 += __shfl_xor_sync(0xffffffffu, sum0, 1);
            sum0 += __shfl_xor_sync(0xffffffffu, sum0, 2);
            sum1 += __shfl_xor_sync(0xffffffffu, sum1, 1);
            sum1 += __shfl_xor_sync(0xffffffffu, sum1, 2);
            lrun0 = lrun0*alpha0 + sum0;
            lrun1 = lrun1*alpha1 + sum1;
            mrun0 = mnew0; mrun1 = mnew1;

            #pragma unroll
            for (int nd = 0; nd < 8; nd++) {
                o[nd][0] *= alpha0; o[nd][1] *= alpha0;
                o[nd][2] *= alpha1; o[nd][3] *= alpha1;
            }

            #pragma unroll
            for (int kk = 0; kk < 4; kk++) {
                #pragma unroll
                for (int np = 0; np < 4; np++) {
                    u32 v0, v1, v2, v3;
                    ldsm4t(v0, v1, v2, v3,
                           Vt + (kk*16 + (mid & 1)*8 + rr)*KP + np*16 + (mid & 2)*4);
                    mma16816(o[2*np],   pa[kk], v0, v1);
                    mma16816(o[2*np+1], pa[kk], v2, v3);
                }
            }
        }

        __syncthreads();
        if (j + 2 < numj) {
            const size_t kbase = (size_t)(j + 2)*AK;
            __nv_bfloat16* Kd = Ks + (j & 1)*AK*KP;
            __nv_bfloat16* Vd = Vs + (j & 1)*AK*KP;
            #pragma unroll
            for (int l = 0; l < 2; l++) {
                int i = tid + l*256;
                int r = i >> 3, c = i & 7;
                cpa16(Kd + r*KP + c*8, Kg + (kbase + r)*DHEAD + c*8);
                cpa16(Vd + r*KP + c*8, Vg + (kbase + r)*DHEAD + c*8);
            }
        }
        cpa_commit();
    }

    float inv0 = 1.f / lrun0, inv1 = 1.f / lrun1;
    __nv_bfloat16* op = g_o + ((size_t)(b*SEQ) + (size_t)qi*AQ)*DMODEL + h*DHEAD;
    const int r0 = w*16 + rq;
    #pragma unroll
    for (int nd = 0; nd < 8; nd++) {
        int cidx = nd*8 + qd*2;
        *(__nv_bfloat162*)(op + (size_t)r0*DMODEL + cidx) =
            __floats2bfloat162_rn(o[nd][0]*inv0, o[nd][1]*inv0);
        *(__nv_bfloat162*)(op + (size_t)(r0+8)*DMODEL + cidx) =
            __floats2bfloat162_rn(o[nd][2]*inv1, o[nd][3]*inv1);
    }
}

extern "C" void kernel_launch(void* const* d_in, const int* in_sizes, int n_in,
                              void* d_out, int out_size)
{
    const float* x     = (const float*)d_in[0];
    const float* Wq    = (const float*)d_in[1];
    const float* Wk    = (const float*)d_in[2];
    const float* Wv    = (const float*)d_in[3];
    const float* Wo    = (const float*)d_in[4];
    const float* bo    = (const float*)d_in[5];
    const float* gamma = (const float*)d_in[6];
    const float* beta  = (const float*)d_in[7];
    float* out = (float*)d_out;

    cudaFuncSetAttribute(gemm_kernel, cudaFuncAttributeMaxDynamicSharedMemorySize, GEMM_SMEM);
    cudaFuncSetAttribute(attn_kernel, cudaFuncAttributeMaxDynamicSharedMemorySize, ATTN_SMEM);

    ln_kernel<<<MTOK, 256>>>(x, gamma, beta);
    convw_kernel<<<dim3(DMODEL*DMODEL/1024, 4), 256>>>(Wq, Wk, Wv, Wo);

    dim3 gqkv(DMODEL/BN, MTOK/BM, 3);
    gemm_kernel<<<gqkv, 128, GEMM_SMEM>>>(nullptr, nullptr, 0);

    dim3 ag(SEQ/AQ, NHEAD, BATCH);
    attn_kernel<<<ag, 256, ATTN_SMEM>>>();

    dim3 go(DMODEL/BN, MTOK/BM, 1);
    gemm_kernel<<<go, 128, GEMM_SMEM>>>(bo, out, 3);
}

// round 5
// speedup vs baseline: 5.4763x; 1.0136x over previous
#include <cuda_runtime.h>
#include <cuda_bf16.h>
#include <cstdint>

typedef unsigned int u32;

#define BATCH 2
#define SEQ   2048
#define DMODEL 1024
#define NHEAD 16
#define DHEAD 64
#define MTOK  (BATCH*SEQ)
#define EPS   1e-5f
#define QSCALE (0.125f*1.44269504f)

__device__ float          g_xn [MTOK*DMODEL];
__device__ __nv_bfloat16  g_xnb[MTOK*DMODEL];
__device__ __nv_bfloat16  g_wb [4][DMODEL*DMODEL];
__device__ __nv_bfloat16  g_q  [MTOK*DMODEL];
__device__ __nv_bfloat16  g_k  [MTOK*DMODEL];
__device__ __nv_bfloat16  g_v  [MTOK*DMODEL];
__device__ __nv_bfloat16  g_o  [MTOK*DMODEL];

__device__ __forceinline__ void cpa16(void* s, const void* g) {
    u32 sa = (u32)__cvta_generic_to_shared(s);
    asm volatile("cp.async.cg.shared.global [%0], [%1], 16;\n" :: "r"(sa), "l"(g));
}
__device__ __forceinline__ void cpa_commit() { asm volatile("cp.async.commit_group;\n"); }
template<int N> __device__ __forceinline__ void cpa_wait() {
    asm volatile("cp.async.wait_group %0;\n" :: "n"(N));
}
__device__ __forceinline__ u32 packbf2(float a, float b) {
    __nv_bfloat162 t = __floats2bfloat162_rn(a, b);
    return *(u32*)&t;
}
__device__ __forceinline__ void mma16816(float* c, const u32* a, u32 b0, u32 b1) {
    asm volatile("mma.sync.aligned.m16n8k16.row.col.f32.bf16.bf16.f32 "
        "{%0,%1,%2,%3}, {%4,%5,%6,%7}, {%8,%9}, {%0,%1,%2,%3};\n"
        : "+f"(c[0]), "+f"(c[1]), "+f"(c[2]), "+f"(c[3])
        : "r"(a[0]), "r"(a[1]), "r"(a[2]), "r"(a[3]), "r"(b0), "r"(b1));
}
__device__ __forceinline__ void ldsm4(u32* d, const __nv_bfloat16* p) {
    u32 addr = (u32)__cvta_generic_to_shared(p);
    asm volatile("ldmatrix.sync.aligned.m8n8.x4.shared.b16 {%0,%1,%2,%3}, [%4];\n"
        : "=r"(d[0]), "=r"(d[1]), "=r"(d[2]), "=r"(d[3]) : "r"(addr));
}
__device__ __forceinline__ void ldsm4t(u32& d0, u32& d1, u32& d2, u32& d3, const __nv_bfloat16* p) {
    u32 addr = (u32)__cvta_generic_to_shared(p);
    asm volatile("ldmatrix.sync.aligned.m8n8.x4.trans.shared.b16 {%0,%1,%2,%3}, [%4];\n"
        : "=r"(d0), "=r"(d1), "=r"(d2), "=r"(d3) : "r"(addr));
}
// exp2 of two packed bf16 values (MUFU once per pair)
__device__ __forceinline__ u32 ex2_bf16x2(u32 d) {
    u32 r;
    asm("ex2.approx.ftz.bf16x2 %0, %1;" : "=r"(r) : "r"(d));
    return r;
}

__global__ __launch_bounds__(256)
void ln_kernel(const float* __restrict__ x,
               const float* __restrict__ gamma,
               const float* __restrict__ beta)
{
    __shared__ float red1[8], red2[8];
    __shared__ float s_mean, s_rstd;
    const int row = blockIdx.x;
    const int tid = threadIdx.x;

    float4 v = ((const float4*)(x + (size_t)row*DMODEL))[tid];
    float s1 = v.x + v.y + v.z + v.w;
    float s2 = v.x*v.x + v.y*v.y + v.z*v.z + v.w*v.w;
    #pragma unroll
    for (int o = 16; o > 0; o >>= 1) {
        s1 += __shfl_xor_sync(0xffffffffu, s1, o);
        s2 += __shfl_xor_sync(0xffffffffu, s2, o);
    }
    if ((tid & 31) == 0) { red1[tid >> 5] = s1; red2[tid >> 5] = s2; }
    __syncthreads();
    if (tid == 0) {
        float t1 = 0.f, t2 = 0.f;
        #pragma unroll
        for (int i = 0; i < 8; i++) { t1 += red1[i]; t2 += red2[i]; }
        float mean = t1 * (1.f/DMODEL);
        float var  = t2 * (1.f/DMODEL) - mean*mean;
        s_mean = mean;
        s_rstd = rsqrtf(var + EPS);
    }
    __syncthreads();
    const float mean = s_mean, rstd = s_rstd;

    float4 g  = ((const float4*)gamma)[tid];
    float4 bt = ((const float4*)beta )[tid];
    float4 o;
    o.x = (v.x - mean)*rstd*g.x + bt.x;
    o.y = (v.y - mean)*rstd*g.y + bt.y;
    o.z = (v.z - mean)*rstd*g.z + bt.z;
    o.w = (v.w - mean)*rstd*g.w + bt.w;
    ((float4*)(g_xn + (size_t)row*DMODEL))[tid] = o;
    __nv_bfloat162* dst = (__nv_bfloat162*)(g_xnb + (size_t)row*DMODEL);
    dst[2*tid]   = __floats2bfloat162_rn(o.x, o.y);
    dst[2*tid+1] = __floats2bfloat162_rn(o.z, o.w);
}

__global__ __launch_bounds__(256)
void convw_kernel(const float* __restrict__ Wq, const float* __restrict__ Wk,
                  const float* __restrict__ Wv, const float* __restrict__ Wo)
{
    const float* src = (blockIdx.y == 0) ? Wq : (blockIdx.y == 1) ? Wk :
                       (blockIdx.y == 2) ? Wv : Wo;
    __nv_bfloat162* dst = (__nv_bfloat162*)g_wb[blockIdx.y];
    int i = blockIdx.x*256 + threadIdx.x;
    float4 v = ((const float4*)src)[i];
    dst[2*i]   = __floats2bfloat162_rn(v.x, v.y);
    dst[2*i+1] = __floats2bfloat162_rn(v.z, v.w);
}

// ---------------- GEMM: 256 thr, 2x4 warps of 64x32, 4-stage cp.async ----------------
#define BM 128
#define BN 128
#define BK 32
#define LDA 40
#define LDB 136
#define NSTG 4
#define GEMM_SMEM (NSTG*(BM*LDA + BK*LDB)*2)

__global__ __launch_bounds__(256)
void gemm_kernel(const float* __restrict__ bias, float* __restrict__ outf, int mode_base)
{
    extern __shared__ char smem_raw[];
    __nv_bfloat16* As = (__nv_bfloat16*)smem_raw;
    __nv_bfloat16* Bs = As + NSTG*BM*LDA;

    const int mode = mode_base + blockIdx.z;
    const __nv_bfloat16* A  = (mode == 3) ? g_o : g_xnb;
    const __nv_bfloat16* Bw = g_wb[mode];
    __nv_bfloat16* outb = (mode == 0) ? g_q : (mode == 1) ? g_k :
                          (mode == 2) ? g_v : nullptr;

    const int tid  = threadIdx.x;
    const int w    = tid >> 5;
    const int lane = tid & 31;
    const int wm = w >> 2, wn = w & 3;          // 2x4 warp grid, warp tile 64x32
    const int bn = blockIdx.x, bm = blockIdx.y;
    const int mid = lane >> 3, rr = lane & 7;
    const int rq = lane >> 2, qd = lane & 3;

    auto prefetch = [&](int kt, int st) {
        __nv_bfloat16* As_s = As + st*BM*LDA;
        __nv_bfloat16* Bs_s = Bs + st*BK*LDB;
        #pragma unroll
        for (int l = 0; l < 2; l++) {                       // A: 128x32 = 512 x 16B
            int i = tid + l*256;
            int r = i >> 2, c = i & 3;
            cpa16(As_s + r*LDA + c*8,
                  A + (size_t)(bm*BM + r)*DMODEL + kt*BK + c*8);
        }
        #pragma unroll
        for (int l = 0; l < 2; l++) {                       // B: 32x128 = 512 x 16B
            int i = tid + l*256;
            int r = i >> 4, c = i & 15;
            cpa16(Bs_s + r*LDB + c*8,
                  Bw + (size_t)(kt*BK + r)*DMODEL + bn*BN + c*8);
        }
    };

    float acc[4][4][4];
    #pragma unroll
    for (int mi = 0; mi < 4; mi++)
        #pragma unroll
        for (int nf = 0; nf < 4; nf++)
            #pragma unroll
            for (int e = 0; e < 4; e++) acc[mi][nf][e] = 0.f;

    prefetch(0, 0); cpa_commit();
    prefetch(1, 1); cpa_commit();
    prefetch(2, 2); cpa_commit();

    const int NT = DMODEL / BK;   // 32
    for (int kt = 0; kt < NT; kt++) {
        cpa_wait<2>();
        __syncthreads();
        const int st = kt & 3;
        __nv_bfloat16* As_s = As + st*BM*LDA;
        __nv_bfloat16* Bs_s = Bs + st*BK*LDB;
        #pragma unroll
        for (int kk = 0; kk < 2; kk++) {
            u32 a[4][4];
            #pragma unroll
            for (int mi = 0; mi < 4; mi++)
                ldsm4(a[mi], As_s + (wm*64 + mi*16 + (mid & 1)*8 + rr)*LDA
                             + kk*16 + (mid & 2)*4);
            #pragma unroll
            for (int nt = 0; nt < 2; nt++) {
                u32 b0, b1, b2, b3;
                ldsm4t(b0, b1, b2, b3,
                       Bs_s + (kk*16 + (mid & 1)*8 + rr)*LDB
                       + wn*32 + nt*16 + (mid & 2)*4);
                #pragma unroll
                for (int mi = 0; mi < 4; mi++) {
                    mma16816(acc[mi][2*nt],   a[mi], b0, b1);
                    mma16816(acc[mi][2*nt+1], a[mi], b2, b3);
                }
            }
        }
        if (kt + 3 < NT) prefetch(kt + 3, (kt + 3) & 3);
        cpa_commit();
    }

    if (mode == 3) {
        #pragma unroll
        for (int mi = 0; mi < 4; mi++) {
            int r0 = bm*BM + wm*64 + mi*16 + rq;
            #pragma unroll
            for (int nf = 0; nf < 4; nf++) {
                int c0 = bn*BN + wn*32 + nf*8 + qd*2;
                float b0 = bias[c0], b1 = bias[c0+1];
                float2 x0 = *(const float2*)(g_xn + (size_t)r0*DMODEL + c0);
                float2 x1 = *(const float2*)(g_xn + (size_t)(r0+8)*DMODEL + c0);
                float2 o0 = { acc[mi][nf][0] + b0 + x0.x, acc[mi][nf][1] + b1 + x0.y };
                float2 o1 = { acc[mi][nf][2] + b0 + x1.x, acc[mi][nf][3] + b1 + x1.y };
                *(float2*)(outf + (size_t)r0*DMODEL + c0)     = o0;
                *(float2*)(outf + (size_t)(r0+8)*DMODEL + c0) = o1;
            }
        }
    } else {
        const float scale = (mode == 0) ? QSCALE : 1.0f;
        #pragma unroll
        for (int mi = 0; mi < 4; mi++) {
            int m0 = bm*BM + wm*64 + mi*16 + rq;
            int b0i = m0 >> 11, t0 = m0 & 2047;
            int b1i = (m0+8) >> 11, t1 = (m0+8) & 2047;
            #pragma unroll
            for (int nf = 0; nf < 4; nf++) {
                int n = bn*BN + wn*32 + nf*8 + qd*2;
                int h = n >> 6, d = n & 63;
                *(__nv_bfloat162*)(outb + (((size_t)(b0i*NHEAD + h))*SEQ + t0)*DHEAD + d) =
                    __floats2bfloat162_rn(acc[mi][nf][0]*scale, acc[mi][nf][1]*scale);
                *(__nv_bfloat162*)(outb + (((size_t)(b1i*NHEAD + h))*SEQ + t1)*DHEAD + d) =
                    __floats2bfloat162_rn(acc[mi][nf][2]*scale, acc[mi][nf][3]*scale);
            }
        }
    }
}

// ---------------- Flash attention (register FA2, bf16x2 exp2) ----------------
#define AQ 128
#define AK 64
#define KP 72
#define ATTN_SMEM ((AQ*KP + 2*AK*KP + 2*AK*KP)*2)

__global__ __launch_bounds__(256, 2)
void attn_kernel()
{
    extern __shared__ char smem_raw[];
    __nv_bfloat16* Qs = (__nv_bfloat16*)smem_raw;
    __nv_bfloat16* Ks = Qs + AQ*KP;
    __nv_bfloat16* Vs = Ks + 2*AK*KP;

    const int tid  = threadIdx.x;
    const int w    = tid >> 5;
    const int lane = tid & 31;
    const int qi = (int)gridDim.x - 1 - (int)blockIdx.x;
    const int h  = blockIdx.y, b = blockIdx.z;
    const size_t head_base = ((size_t)(b*NHEAD + h))*SEQ*DHEAD;
    const __nv_bfloat16* Kg = g_k + head_base;
    const __nv_bfloat16* Vg = g_v + head_base;

    const int numj = 2*qi + 2;

    {
        const __nv_bfloat16* qptr = g_q + head_base + (size_t)qi*AQ*DHEAD;
        #pragma unroll
        for (int l = 0; l < 4; l++) {
            int i = tid + l*256;
            int r = i >> 3, c = i & 7;
            cpa16(Qs + r*KP + c*8, qptr + r*DHEAD + c*8);
        }
        #pragma unroll
        for (int l = 0; l < 2; l++) {
            int i = tid + l*256;
            int r = i >> 3, c = i & 7;
            cpa16(Ks + r*KP + c*8, Kg + r*DHEAD + c*8);
            cpa16(Vs + r*KP + c*8, Vg + r*DHEAD + c*8);
        }
        cpa_commit();
    }
    if (numj > 1) {
        #pragma unroll
        for (int l = 0; l < 2; l++) {
            int i = tid + l*256;
            int r = i >> 3, c = i & 7;
            cpa16(Ks + AK*KP + r*KP + c*8, Kg + (size_t)(AK + r)*DHEAD + c*8);
            cpa16(Vs + AK*KP + r*KP + c*8, Vg + (size_t)(AK + r)*DHEAD + c*8);
        }
    }
    cpa_commit();

    const int rq = lane >> 2;
    const int qd = lane & 3;
    const int row0 = qi*AQ + w*16 + rq;

    u32 qa[4][4];
    float o[8][4];
    #pragma unroll
    for (int nd = 0; nd < 8; nd++)
        #pragma unroll
        for (int e = 0; e < 4; e++) o[nd][e] = 0.f;
    float mrun0 = -INFINITY, mrun1 = -INFINITY, lrun0 = 0.f, lrun1 = 0.f;

    const int mid = lane >> 3, rr = lane & 7;

    for (int j = 0; j < numj; j++) {
        cpa_wait<1>();
        __syncthreads();

        if (j == 0) {
            #pragma unroll
            for (int kk = 0; kk < 4; kk++)
                ldsm4(qa[kk], Qs + (w*16 + (mid & 1)*8 + rr)*KP + kk*16 + (mid & 2)*4);
        }

        const int colbase = j*AK;
        const bool active = colbase <= qi*AQ + w*16 + 15;
        __nv_bfloat16* Kt = Ks + (j & 1)*AK*KP;
        __nv_bfloat16* Vt = Vs + (j & 1)*AK*KP;

        if (active) {
            float c[8][4];
            #pragma unroll
            for (int nf = 0; nf < 8; nf++)
                #pragma unroll
                for (int e = 0; e < 4; e++) c[nf][e] = 0.f;

            #pragma unroll
            for (int kk = 0; kk < 4; kk++) {
                #pragma unroll
                for (int np = 0; np < 4; np++) {
                    u32 b0, b1, b2, b3;
                    u32 addr = (u32)__cvta_generic_to_shared(
                        Kt + (np*16 + (mid & 2)*4 + rr)*KP + kk*16 + (mid & 1)*8);
                    asm volatile("ldmatrix.sync.aligned.m8n8.x4.shared.b16 {%0,%1,%2,%3}, [%4];\n"
                        : "=r"(b0), "=r"(b1), "=r"(b2), "=r"(b3) : "r"(addr));
                    mma16816(c[2*np],   qa[kk], b0, b1);
                    mma16816(c[2*np+1], qa[kk], b2, b3);
                }
            }

            const bool needmask = (colbase + AK - 1) > (qi*AQ + w*16);
            float tm0 = -INFINITY, tm1 = -INFINITY;
            #pragma unroll
            for (int nf = 0; nf < 8; nf++) {
                int cg = colbase + nf*8 + qd*2;
                float s0 = c[nf][0], s1 = c[nf][1];
                float s2 = c[nf][2], s3 = c[nf][3];
                if (needmask) {
                    if (cg     > row0    ) s0 = -INFINITY;
                    if (cg + 1 > row0    ) s1 = -INFINITY;
                    if (cg     > row0 + 8) s2 = -INFINITY;
                    if (cg + 1 > row0 + 8) s3 = -INFINITY;
                }
                c[nf][0] = s0; c[nf][1] = s1; c[nf][2] = s2; c[nf][3] = s3;
                tm0 = fmaxf(tm0, fmaxf(s0, s1));
                tm1 = fmaxf(tm1, fmaxf(s2, s3));
            }
            tm0 = fmaxf(tm0, __shfl_xor_sync(0xffffffffu, tm0, 1));
            tm0 = fmaxf(tm0, __shfl_xor_sync(0xffffffffu, tm0, 2));
            tm1 = fmaxf(tm1, __shfl_xor_sync(0xffffffffu, tm1, 1));
            tm1 = fmaxf(tm1, __shfl_xor_sync(0xffffffffu, tm1, 2));

            float mnew0 = fmaxf(mrun0, tm0), mnew1 = fmaxf(mrun1, tm1);
            float alpha0 = exp2f(mrun0 - mnew0), alpha1 = exp2f(mrun1 - mnew1);
            float sum0 = 0.f, sum1 = 0.f;
            u32 pa[4][4];
            #pragma unroll
            for (int nf = 0; nf < 8; nf++) {
                // exp2 computed directly in bf16x2 (one MUFU per pair)
                u32 lo = ex2_bf16x2(packbf2(c[nf][0] - mnew0, c[nf][1] - mnew0));
                u32 hi = ex2_bf16x2(packbf2(c[nf][2] - mnew1, c[nf][3] - mnew1));
                sum0 += __uint_as_float(lo << 16) + __uint_as_float(lo & 0xffff0000u);
                sum1 += __uint_as_float(hi << 16) + __uint_as_float(hi & 0xffff0000u);
                int kk = nf >> 1;
                if ((nf & 1) == 0) { pa[kk][0] = lo; pa[kk][1] = hi; }
                else               { pa[kk][2] = lo; pa[kk][3] = hi; }
            }
            sum0 += __shfl_xor_sync(0xffffffffu, sum0, 1);
            sum0 += __shfl_xor_sync(0xffffffffu, sum0, 2);
            sum1 += __shfl_xor_sync(0xffffffffu, sum1, 1);
            sum1 += __shfl_xor_sync(0xffffffffu, sum1, 2);
            lrun0 = lrun0*alpha0 + sum0;
            lrun1 = lrun1*alpha1 + sum1;
            mrun0 = mnew0; mrun1 = mnew1;

            #pragma unroll
            for (int nd = 0; nd < 8; nd++) {
                o[nd][0] *= alpha0; o[nd][1] *= alpha0;
                o[nd][2] *= alpha1; o[nd][3] *= alpha1;
            }

            #pragma unroll
            for (int kk = 0; kk < 4; kk++) {
                #pragma unroll
                for (int np = 0; np < 4; np++) {
                    u32 v0, v1, v2, v3;
                    ldsm4t(v0, v1, v2, v3,
                           Vt + (kk*16 + (mid & 1)*8 + rr)*KP + np*16 + (mid & 2)*4);
                    mma16816(o[2*np],   pa[kk], v0, v1);
                    mma16816(o[2*np+1], pa[kk], v2, v3);
                }
            }
        }

        __syncthreads();
        if (j + 2 < numj) {
            const size_t kbase = (size_t)(j + 2)*AK;
            __nv_bfloat16* Kd = Ks + (j & 1)*AK*KP;
            __nv_bfloat16* Vd = Vs + (j & 1)*AK*KP;
            #pragma unroll
            for (int l = 0; l < 2; l++) {
                int i = tid + l*256;
                int r = i >> 3, c = i & 7;
                cpa16(Kd + r*KP + c*8, Kg + (kbase + r)*DHEAD + c*8);
                cpa16(Vd + r*KP + c*8, Vg + (kbase + r)*DHEAD + c*8);
            }
        }
        cpa_commit();
    }

    float inv0 = 1.f / lrun0, inv1 = 1.f / lrun1;
    __nv_bfloat16* op = g_o + ((size_t)(b*SEQ) + (size_t)qi*AQ)*DMODEL + h*DHEAD;
    const int r0 = w*16 + rq;
    #pragma unroll
    for (int nd = 0; nd < 8; nd++) {
        int cidx = nd*8 + qd*2;
        *(__nv_bfloat162*)(op + (size_t)r0*DMODEL + cidx) =
            __floats2bfloat162_rn(o[nd][0]*inv0, o[nd][1]*inv0);
        *(__nv_bfloat162*)(op + (size_t)(r0+8)*DMODEL + cidx) =
            __floats2bfloat162_rn(o[nd][2]*inv1, o[nd][3]*inv1);
    }
}

extern "C" void kernel_launch(void* const* d_in, const int* in_sizes, int n_in,
                              void* d_out, int out_size)
{
    const float* x     = (const float*)d_in[0];
    const float* Wq    = (const float*)d_in[1];
    const float* Wk    = (const float*)d_in[2];
    const float* Wv    = (const float*)d_in[3];
    const float* Wo    = (const float*)d_in[4];
    const float* bo    = (const float*)d_in[5];
    const float* gamma = (const float*)d_in[6];
    const float* beta  = (const float*)d_in[7];
    float* out = (float*)d_out;

    cudaFuncSetAttribute(gemm_kernel, cudaFuncAttributeMaxDynamicSharedMemorySize, GEMM_SMEM);
    cudaFuncSetAttribute(attn_kernel, cudaFuncAttributeMaxDynamicSharedMemorySize, ATTN_SMEM);

    ln_kernel<<<MTOK, 256>>>(x, gamma, beta);
    convw_kernel<<<dim3(DMODEL*DMODEL/1024, 4), 256>>>(Wq, Wk, Wv, Wo);

    dim3 gqkv(DMODEL/BN, MTOK/BM, 3);
    gemm_kernel<<<gqkv, 256, GEMM_SMEM>>>(nullptr, nullptr, 0);

    dim3 ag(SEQ/AQ, NHEAD, BATCH);
    attn_kernel<<<ag, 256, ATTN_SMEM>>>();

    dim3 go(DMODEL/BN, MTOK/BM, 1);
    gemm_kernel<<<go, 256, GEMM_SMEM>>>(bo, out, 3);
}